// round 14
// baseline (speedup 1.0000x reference)
#include <cuda_runtime.h>
#include <cuda_fp16.h>
#include <math.h>
#include <stdint.h>

#define NN   50000
#define NF   256
#define NHID 128
#define KHOP 4
#define NC   512      // KHOP * NHID
#define NE   800000
#define NO   64
#define SA   40       // smem row stride in fp16 elems (80B, conflict-free frags)

#define NBIN (KHOP * NN)        // 200000 row bins across all hops
#define NET  (KHOP * NE)        // 3200000 edges total
#define SCAN_BLK   256
#define SCAN_PER   16
#define SCAN_CHUNK (SCAN_BLK * SCAN_PER)   // 4096
#define SCAN_NB    49                       // ceil(NBIN / SCAN_CHUNK)

// ---------------------------------------------------------------------------
// Scratch (__device__ globals per harness allocation rules)
// ---------------------------------------------------------------------------
__device__ __half g_h[(size_t)NN * NC];    // post-linear features, fp16 (51.2MB)
__device__ __half g_agg[(size_t)NN * NC];  // SpMM output, fp16 (51.2MB):
                                           // h+agg = 102MB < 126MB L2 -> both
                                           // resident during spmm
__device__ __half g_wt[KHOP * NHID * NF];  // W transposed [hop][n][k], fp16
__device__ __half g_wot[NO * NC];          // W_out transposed [n][k], fp16
// CSR build (recomputed every call; deterministic work)
__device__ int  g_cnt[NBIN];
__device__ int  g_rowptr[NBIN + 1];
__device__ int  g_cur[NBIN];
__device__ int  g_bsum[SCAN_NB];
__device__ int2 g_edge[NET];               // interleaved (col, val-bits)

// ---------------------------------------------------------------------------
// mma.sync m16n8k16 fp16 -> f32, helpers
// ---------------------------------------------------------------------------
__device__ __forceinline__ void mma16816(float* d, const uint32_t* a, const uint32_t* b) {
    asm volatile(
        "mma.sync.aligned.m16n8k16.row.col.f32.f16.f16.f32 "
        "{%0,%1,%2,%3}, {%4,%5,%6,%7}, {%8,%9}, {%0,%1,%2,%3};\n"
        : "+f"(d[0]), "+f"(d[1]), "+f"(d[2]), "+f"(d[3])
        : "r"(a[0]), "r"(a[1]), "r"(a[2]), "r"(a[3]), "r"(b[0]), "r"(b[1]));
}

__device__ __forceinline__ uint32_t lds32(const __half* p) {
    return *reinterpret_cast<const uint32_t*>(p);
}

// convert 8 floats (2x float4) to 8 packed fp16
__device__ __forceinline__ uint4 cvt8(float4 a, float4 b) {
    union { uint4 u; __half2 s[4]; } U;
    U.s[0] = __floats2half2_rn(a.x, a.y);
    U.s[1] = __floats2half2_rn(a.z, a.w);
    U.s[2] = __floats2half2_rn(b.x, b.y);
    U.s[3] = __floats2half2_rn(b.z, b.w);
    return U.u;
}

__device__ __forceinline__ float elu1(float v) {
    return v > 0.f ? v : (__expf(v) - 1.f);
}

// elu over 8 packed halves (fp16 in, fp16 out; math in f32)
__device__ __forceinline__ uint4 elu8_h(uint4 in) {
    union { uint4 u; __half2 s[4]; } I, O;
    I.u = in;
#pragma unroll
    for (int q = 0; q < 4; q++) {
        float2 f = __half22float2(I.s[q]);
        O.s[q] = __floats2half2_rn(elu1(f.x), elu1(f.y));
    }
    return O.u;
}

// ---------------------------------------------------------------------------
// Prep: zero CSR counters + both weight fp16 transposes, one kernel.
// ---------------------------------------------------------------------------
__global__ __launch_bounds__(256) void prep(const float* __restrict__ W,
                                            const float* __restrict__ Wout) {
    const int idx = blockIdx.x * 256 + threadIdx.x;
    if (idx < NBIN) g_cnt[idx] = 0;
    if (idx < KHOP * NF * NHID) {
        int hop = idx / (NF * NHID);
        int rem = idx - hop * (NF * NHID);
        int k = rem / NHID;
        int n = rem - k * NHID;
        g_wt[(size_t)hop * NHID * NF + (size_t)n * NF + k] = __float2half_rn(W[idx]);
    }
    if (idx < NC * NO) {
        int k = idx / NO;
        int n = idx - k * NO;
        g_wot[(size_t)n * NC + k] = __float2half_rn(Wout[idx]);
    }
}

// ---------------------------------------------------------------------------
// CSR build: histogram -> two-level scan -> scatter (global across hops).
// ---------------------------------------------------------------------------
__global__ __launch_bounds__(256) void hist(const int* __restrict__ erows) {
    int e = blockIdx.x * 256 + threadIdx.x;
    if (e >= NET) return;
    int hop = e / NE;
    atomicAdd(&g_cnt[hop * NN + erows[e]], 1);
}

__global__ __launch_bounds__(SCAN_BLK) void scan1() {
    __shared__ int sh[SCAN_BLK];
    const int t = threadIdx.x;
    const int base = blockIdx.x * SCAN_CHUNK + t * SCAN_PER;
    int v[SCAN_PER];
    int tot = 0;
#pragma unroll
    for (int i = 0; i < SCAN_PER; i++) {
        v[i] = (base + i < NBIN) ? g_cnt[base + i] : 0;
        tot += v[i];
    }
    sh[t] = tot;
    __syncthreads();
    for (int off = 1; off < SCAN_BLK; off <<= 1) {
        int x = (t >= off) ? sh[t - off] : 0;
        __syncthreads();
        sh[t] += x;
        __syncthreads();
    }
    int run = sh[t] - tot;
#pragma unroll
    for (int i = 0; i < SCAN_PER; i++) {
        if (base + i < NBIN) g_rowptr[base + i] = run;
        run += v[i];
    }
    if (t == 0) g_bsum[blockIdx.x] = sh[SCAN_BLK - 1];
}

__global__ __launch_bounds__(256) void scan3() {
    int i = blockIdx.x * 256 + threadIdx.x;
    if (i < NBIN) {
        const int nb = i / SCAN_CHUNK;
        int pre = 0;
        for (int b = 0; b < nb; b++) pre += g_bsum[b];
        int v = g_rowptr[i] + pre;
        g_rowptr[i] = v;
        g_cur[i] = v;
    }
    if (i == 0) g_rowptr[NBIN] = NET;
}

__global__ __launch_bounds__(256) void scatter(const int* __restrict__ erows,
                                               const int* __restrict__ ecols,
                                               const float* __restrict__ evals) {
    int e = blockIdx.x * 256 + threadIdx.x;
    if (e >= NET) return;
    int hop = e / NE;
    int pos = atomicAdd(&g_cur[hop * NN + erows[e]], 1);
    g_edge[pos] = make_int2(ecols[e], __float_as_int(evals[e]));
}

// ---------------------------------------------------------------------------
// GEMM1 (tensor): g_h[n, hop*128+j] = fp16(x @ W[hop] + b[hop])
// Single-pass pure-fp16 mma. CTA 128x128, BK=32, 8 warps (4m x 2n).
// ---------------------------------------------------------------------------
__global__ __launch_bounds__(256) void gemm1_mma(const float* __restrict__ x,
                                                 const float* __restrict__ bias) {
    const int hop = blockIdx.x;
    const int m0  = blockIdx.y * 128;

    __shared__ __half As[128 * SA];
    __shared__ __half Bs[128 * SA];

    const int t    = threadIdx.x;
    const int wid  = t >> 5, lane = t & 31;
    const int wm   = wid >> 1, wn = wid & 1;
    const int g    = lane >> 2, t4 = lane & 3;

    const int lr = t >> 2;          // 0..63
    const int lk = (t & 3) * 8;     // 0,8,16,24

    const __half* wt = g_wt + (size_t)hop * NHID * NF;

    float acc[2][8][4];
#pragma unroll
    for (int i = 0; i < 2; i++)
#pragma unroll
        for (int j = 0; j < 8; j++)
#pragma unroll
            for (int q = 0; q < 4; q++) acc[i][j][q] = 0.f;

    const float4 zf = make_float4(0.f, 0.f, 0.f, 0.f);
    float4 fx0a, fx0b, fx1a, fx1b;
    uint4 pb0, pb1;

    const int r0 = m0 + lr, r1 = m0 + lr + 64;
    {   // prefetch k0 = 0
        fx0a = (r0 < NN) ? *(const float4*)(x + (size_t)r0 * NF + lk)     : zf;
        fx0b = (r0 < NN) ? *(const float4*)(x + (size_t)r0 * NF + lk + 4) : zf;
        fx1a = (r1 < NN) ? *(const float4*)(x + (size_t)r1 * NF + lk)     : zf;
        fx1b = (r1 < NN) ? *(const float4*)(x + (size_t)r1 * NF + lk + 4) : zf;
        pb0  = *(const uint4*)(wt + (size_t)lr * NF + lk);
        pb1  = *(const uint4*)(wt + (size_t)(lr + 64) * NF + lk);
    }

    for (int k0 = 0; k0 < NF; k0 += 32) {
        __syncthreads();
        *(uint4*)&As[lr * SA + lk]        = cvt8(fx0a, fx0b);
        *(uint4*)&As[(lr + 64) * SA + lk] = cvt8(fx1a, fx1b);
        *(uint4*)&Bs[lr * SA + lk]        = pb0;
        *(uint4*)&Bs[(lr + 64) * SA + lk] = pb1;
        __syncthreads();

        const int kn = k0 + 32;
        if (kn < NF) {   // prefetch next K-block
            fx0a = (r0 < NN) ? *(const float4*)(x + (size_t)r0 * NF + kn + lk)     : zf;
            fx0b = (r0 < NN) ? *(const float4*)(x + (size_t)r0 * NF + kn + lk + 4) : zf;
            fx1a = (r1 < NN) ? *(const float4*)(x + (size_t)r1 * NF + kn + lk)     : zf;
            fx1b = (r1 < NN) ? *(const float4*)(x + (size_t)r1 * NF + kn + lk + 4) : zf;
            pb0  = *(const uint4*)(wt + (size_t)lr * NF + kn + lk);
            pb1  = *(const uint4*)(wt + (size_t)(lr + 64) * NF + kn + lk);
        }

#pragma unroll
        for (int ks = 0; ks < 2; ks++) {
            const int kb = ks * 16 + 2 * t4;
            uint32_t a[2][4];
#pragma unroll
            for (int mf = 0; mf < 2; mf++) {
                const int rb = (wm * 32 + mf * 16 + g) * SA + kb;
                a[mf][0] = lds32(&As[rb]);
                a[mf][1] = lds32(&As[rb + 8 * SA]);
                a[mf][2] = lds32(&As[rb + 8]);
                a[mf][3] = lds32(&As[rb + 8 * SA + 8]);
            }
#pragma unroll
            for (int nf = 0; nf < 8; nf++) {
                const int nb = (wn * 64 + nf * 8 + g) * SA + kb;
                uint32_t bb[2];
                bb[0] = lds32(&Bs[nb]); bb[1] = lds32(&Bs[nb + 8]);
#pragma unroll
                for (int mf = 0; mf < 2; mf++)
                    mma16816(acc[mf][nf], a[mf], bb);
            }
        }
    }

    const int colbase = wn * 64 + 2 * t4;
#pragma unroll
    for (int mf = 0; mf < 2; mf++) {
        const int row = m0 + wm * 32 + mf * 16 + g;
#pragma unroll
        for (int nf = 0; nf < 8; nf++) {
            const int col = colbase + nf * 8;
            const float2 bv = *(const float2*)(bias + hop * NHID + col);
            if (row < NN) {
                *(__half2*)(g_h + (size_t)row * NC + hop * NHID + col) =
                    __floats2half2_rn(acc[mf][nf][0] + bv.x, acc[mf][nf][1] + bv.y);
            }
            if (row + 8 < NN) {
                *(__half2*)(g_h + (size_t)(row + 8) * NC + hop * NHID + col) =
                    __floats2half2_rn(acc[mf][nf][2] + bv.x, acc[mf][nf][3] + bv.y);
            }
        }
    }
}

// ---------------------------------------------------------------------------
// CSR SpMM, all hops in one launch. One warp per row, fp32 register
// accumulation, single fp16 write. Lane owns 4 features (8B gather/edge).
// 8-wide gather unroll for deeper per-warp MLP.
// ---------------------------------------------------------------------------
__global__ __launch_bounds__(256) void spmm_csr() {
    const int row  = (blockIdx.x * 256 + threadIdx.x) >> 5;
    const int lane = threadIdx.x & 31;
    if (row >= NN) return;
    const int hop = blockIdx.y;

    const int bin = hop * NN + row;
    const int s = g_rowptr[bin];
    const int e = g_rowptr[bin + 1];

    const __half* hb = g_h + hop * NHID + lane * 4;
    float4 acc = make_float4(0.f, 0.f, 0.f, 0.f);

    for (int p = s; p < e; p += 32) {
        const int n = min(32, e - p);
        int2 ed = (lane < n) ? g_edge[p + lane] : make_int2(0, 0);
        const int   c = ed.x;
        const float v = __int_as_float(ed.y);
        int j = 0;
        for (; j + 8 <= n; j += 8) {
            int jc[8]; float jv[8]; uint2 u[8];
#pragma unroll
            for (int q = 0; q < 8; q++) {
                jc[q] = __shfl_sync(0xffffffffu, c, j + q);
                jv[q] = __shfl_sync(0xffffffffu, v, j + q);
            }
#pragma unroll
            for (int q = 0; q < 8; q++)
                u[q] = *(const uint2*)(hb + (size_t)jc[q] * NC);
#pragma unroll
            for (int q = 0; q < 8; q++) {
                float2 a = __half22float2(*(__half2*)&u[q].x);
                float2 b = __half22float2(*(__half2*)&u[q].y);
                acc.x = fmaf(jv[q], a.x, acc.x);
                acc.y = fmaf(jv[q], a.y, acc.y);
                acc.z = fmaf(jv[q], b.x, acc.z);
                acc.w = fmaf(jv[q], b.y, acc.w);
            }
        }
        for (; j < n; j++) {
            int   cj = __shfl_sync(0xffffffffu, c, j);
            float vj = __shfl_sync(0xffffffffu, v, j);
            uint2 u = *(const uint2*)(hb + (size_t)cj * NC);
            float2 a = __half22float2(*(__half2*)&u.x);
            float2 b = __half22float2(*(__half2*)&u.y);
            acc.x = fmaf(vj, a.x, acc.x); acc.y = fmaf(vj, a.y, acc.y);
            acc.z = fmaf(vj, b.x, acc.z); acc.w = fmaf(vj, b.y, acc.w);
        }
    }

    union { uint2 u; __half2 s[2]; } O;
    O.s[0] = __floats2half2_rn(acc.x, acc.y);
    O.s[1] = __floats2half2_rn(acc.z, acc.w);
    *(uint2*)(g_agg + (size_t)row * NC + hop * NHID + lane * 4) = O.u;
}

// ---------------------------------------------------------------------------
// GEMM2 (tensor): y = elu(agg) @ W_out + b_out. agg is fp16; elu applied
// in the A stage (f32 math, fp16 out). CTA 128x64, BK=32, 8 warps (4m x 2n).
// ---------------------------------------------------------------------------
__global__ __launch_bounds__(256) void gemm2_mma(const float* __restrict__ bout,
                                                 float* __restrict__ y) {
    const int m0 = blockIdx.x * 128;

    __shared__ __half As[128 * SA];
    __shared__ __half Bs[64 * SA];

    const int t   = threadIdx.x;
    const int wid = t >> 5, lane = t & 31;
    const int wm  = wid >> 1, wn = wid & 1;
    const int g   = lane >> 2, t4 = lane & 3;

    const int ar = t >> 1;          // A row 0..127
    const int ac = (t & 1) * 16;    // A col block (16 fp16)
    const int br = t >> 2;          // B row (n) 0..63
    const int bk = (t & 3) * 8;     // B col block (8 fp16)

    const int arow = m0 + ar;
    const bool aok = arow < NN;

    float acc[2][4][4];
#pragma unroll
    for (int i = 0; i < 2; i++)
#pragma unroll
        for (int j = 0; j < 4; j++)
#pragma unroll
            for (int q = 0; q < 4; q++) acc[i][j][q] = 0.f;

    const uint4 z4 = make_uint4(0, 0, 0, 0);
    uint4 pa0, pa1, pb;

    {
        const __half* ap = g_agg + (size_t)arow * NC + ac;
        pa0 = aok ? *(const uint4*)(ap)     : z4;
        pa1 = aok ? *(const uint4*)(ap + 8) : z4;
        pb  = *(const uint4*)(g_wot + (size_t)br * NC + bk);
    }

    for (int k0 = 0; k0 < NC; k0 += 32) {
        __syncthreads();
        *(uint4*)&As[ar * SA + ac]     = elu8_h(pa0);
        *(uint4*)&As[ar * SA + ac + 8] = elu8_h(pa1);
        *(uint4*)&Bs[br * SA + bk]     = pb;
        __syncthreads();

        const int kn = k0 + 32;
        if (kn < NC) {
            const __half* ap = g_agg + (size_t)arow * NC + kn + ac;
            pa0 = aok ? *(const uint4*)(ap)     : z4;
            pa1 = aok ? *(const uint4*)(ap + 8) : z4;
            pb  = *(const uint4*)(g_wot + (size_t)br * NC + kn + bk);
        }

#pragma unroll
        for (int ks = 0; ks < 2; ks++) {
            const int kb = ks * 16 + 2 * t4;
            uint32_t a[2][4];
#pragma unroll
            for (int mf = 0; mf < 2; mf++) {
                const int rb = (wm * 32 + mf * 16 + g) * SA + kb;
                a[mf][0] = lds32(&As[rb]);
                a[mf][1] = lds32(&As[rb + 8 * SA]);
                a[mf][2] = lds32(&As[rb + 8]);
                a[mf][3] = lds32(&As[rb + 8 * SA + 8]);
            }
#pragma unroll
            for (int nf = 0; nf < 4; nf++) {
                const int nb = (wn * 32 + nf * 8 + g) * SA + kb;
                uint32_t bb[2];
                bb[0] = lds32(&Bs[nb]); bb[1] = lds32(&Bs[nb + 8]);
#pragma unroll
                for (int mf = 0; mf < 2; mf++)
                    mma16816(acc[mf][nf], a[mf], bb);
            }
        }
    }

    const int colbase = wn * 32 + 2 * t4;
#pragma unroll
    for (int mf = 0; mf < 2; mf++) {
        const int row = m0 + wm * 32 + mf * 16 + g;
#pragma unroll
        for (int nf = 0; nf < 4; nf++) {
            const int col = colbase + nf * 8;
            const float2 bv = *(const float2*)(bout + col);
            if (row < NN) {
                float2 o;
                o.x = acc[mf][nf][0] + bv.x;
                o.y = acc[mf][nf][1] + bv.y;
                *(float2*)(y + (size_t)row * NO + col) = o;
            }
            if (row + 8 < NN) {
                float2 o;
                o.x = acc[mf][nf][2] + bv.x;
                o.y = acc[mf][nf][3] + bv.y;
                *(float2*)(y + (size_t)(row + 8) * NO + col) = o;
            }
        }
    }
}

// ---------------------------------------------------------------------------
// Launch. Inputs: x, W, b, W_out, b_out, edge_rows, edge_cols, edge_vals.
// ---------------------------------------------------------------------------
extern "C" void kernel_launch(void* const* d_in, const int* in_sizes, int n_in,
                              void* d_out, int out_size) {
    (void)in_sizes; (void)n_in; (void)out_size;
    const float* x     = (const float*)d_in[0];
    const float* W     = (const float*)d_in[1];
    const float* b     = (const float*)d_in[2];
    const float* Wout  = (const float*)d_in[3];
    const float* bout  = (const float*)d_in[4];
    const int*   erows = (const int*)d_in[5];
    const int*   ecols = (const int*)d_in[6];
    const float* evals = (const float*)d_in[7];
    float* y = (float*)d_out;

    // prep (zero counters + weight fp16 transposes) and CSR build
    prep<<<(NBIN + 255) / 256, 256>>>(W, Wout);
    hist<<<NET / 256, 256>>>(erows);
    scan1<<<SCAN_NB, SCAN_BLK>>>();
    scan3<<<(NBIN + 255) / 256, 256>>>();
    scatter<<<NET / 256, 256>>>(erows, ecols, evals);

    // per-hop linear on tensor cores (single-pass fp16), fp16 h output
    gemm1_mma<<<dim3(KHOP, (NN + 127) / 128), 256>>>(x, b);

    // CSR SpMM, all hops in one launch (h + agg both L2-resident, fp16)
    spmm_csr<<<dim3((NN * 32 + 255) / 256, KHOP), 256>>>();

    // elu + output projection on tensor cores (fp16 agg in)
    gemm2_mma<<<(NN + 127) / 128, 256>>>(bout, y);
}

// round 15
// speedup vs baseline: 1.0922x; 1.0922x over previous
#include <cuda_runtime.h>
#include <cuda_fp16.h>
#include <math.h>
#include <stdint.h>

#define NN   50000
#define NF   256
#define NHID 128
#define KHOP 4
#define NC   512      // KHOP * NHID
#define NE   800000
#define NO   64
#define SA   40       // smem row stride in fp16 elems (80B, conflict-free frags)

#define NBIN (KHOP * NN)        // 200000 row bins across all hops
#define NET  (KHOP * NE)        // 3200000 edges total
#define SCAN_BLK   256
#define SCAN_PER   16
#define SCAN_CHUNK (SCAN_BLK * SCAN_PER)   // 4096
#define SCAN_NB    49                       // ceil(NBIN / SCAN_CHUNK)

// ---------------------------------------------------------------------------
// Scratch (__device__ globals per harness allocation rules)
// ---------------------------------------------------------------------------
__device__ __half g_h[(size_t)NN * NC];    // post-linear features, fp16 (51.2MB)
__device__ __half g_agg[(size_t)NN * NC];  // SpMM output, fp16 (51.2MB):
                                           // h+agg = 102MB < 126MB L2
__device__ __half g_wt[KHOP * NHID * NF];  // W transposed [hop][n][k], fp16
__device__ __half g_wot[NO * NC];          // W_out transposed [n][k], fp16
// CSR build (recomputed every call; deterministic work)
__device__ int  g_cnt[NBIN];
__device__ int  g_rowptr[NBIN + 1];
__device__ int  g_cur[NBIN];
__device__ int  g_bsum[SCAN_NB];
__device__ int2 g_edge[NET];               // interleaved (col, val-bits)

// ---------------------------------------------------------------------------
// mma.sync m16n8k16 fp16 -> f32, helpers
// ---------------------------------------------------------------------------
__device__ __forceinline__ void mma16816(float* d, const uint32_t* a, const uint32_t* b) {
    asm volatile(
        "mma.sync.aligned.m16n8k16.row.col.f32.f16.f16.f32 "
        "{%0,%1,%2,%3}, {%4,%5,%6,%7}, {%8,%9}, {%0,%1,%2,%3};\n"
        : "+f"(d[0]), "+f"(d[1]), "+f"(d[2]), "+f"(d[3])
        : "r"(a[0]), "r"(a[1]), "r"(a[2]), "r"(a[3]), "r"(b[0]), "r"(b[1]));
}

__device__ __forceinline__ uint32_t lds32(const __half* p) {
    return *reinterpret_cast<const uint32_t*>(p);
}

// convert 8 floats (2x float4) to 8 packed fp16
__device__ __forceinline__ uint4 cvt8(float4 a, float4 b) {
    union { uint4 u; __half2 s[4]; } U;
    U.s[0] = __floats2half2_rn(a.x, a.y);
    U.s[1] = __floats2half2_rn(a.z, a.w);
    U.s[2] = __floats2half2_rn(b.x, b.y);
    U.s[3] = __floats2half2_rn(b.z, b.w);
    return U.u;
}

__device__ __forceinline__ float elu1(float v) {
    return v > 0.f ? v : (__expf(v) - 1.f);
}

// elu over 8 packed halves (fp16 in, fp16 out; math in f32)
__device__ __forceinline__ uint4 elu8_h(uint4 in) {
    union { uint4 u; __half2 s[4]; } I, O;
    I.u = in;
#pragma unroll
    for (int q = 0; q < 4; q++) {
        float2 f = __half22float2(I.s[q]);
        O.s[q] = __floats2half2_rn(elu1(f.x), elu1(f.y));
    }
    return O.u;
}

// ---------------------------------------------------------------------------
// Prep: zero CSR counters + both weight fp16 transposes, one kernel.
// ---------------------------------------------------------------------------
__global__ __launch_bounds__(256) void prep(const float* __restrict__ W,
                                            const float* __restrict__ Wout) {
    const int idx = blockIdx.x * 256 + threadIdx.x;
    if (idx < NBIN) g_cnt[idx] = 0;
    if (idx < KHOP * NF * NHID) {
        int hop = idx / (NF * NHID);
        int rem = idx - hop * (NF * NHID);
        int k = rem / NHID;
        int n = rem - k * NHID;
        g_wt[(size_t)hop * NHID * NF + (size_t)n * NF + k] = __float2half_rn(W[idx]);
    }
    if (idx < NC * NO) {
        int k = idx / NO;
        int n = idx - k * NO;
        g_wot[(size_t)n * NC + k] = __float2half_rn(Wout[idx]);
    }
}

// ---------------------------------------------------------------------------
// CSR build: histogram -> two-level scan -> scatter (global across hops).
// ---------------------------------------------------------------------------
__global__ __launch_bounds__(256) void hist(const int* __restrict__ erows) {
    int e = blockIdx.x * 256 + threadIdx.x;
    if (e >= NET) return;
    int hop = e / NE;
    atomicAdd(&g_cnt[hop * NN + erows[e]], 1);
}

__global__ __launch_bounds__(SCAN_BLK) void scan1() {
    __shared__ int sh[SCAN_BLK];
    const int t = threadIdx.x;
    const int base = blockIdx.x * SCAN_CHUNK + t * SCAN_PER;
    int v[SCAN_PER];
    int tot = 0;
#pragma unroll
    for (int i = 0; i < SCAN_PER; i++) {
        v[i] = (base + i < NBIN) ? g_cnt[base + i] : 0;
        tot += v[i];
    }
    sh[t] = tot;
    __syncthreads();
    for (int off = 1; off < SCAN_BLK; off <<= 1) {
        int x = (t >= off) ? sh[t - off] : 0;
        __syncthreads();
        sh[t] += x;
        __syncthreads();
    }
    int run = sh[t] - tot;
#pragma unroll
    for (int i = 0; i < SCAN_PER; i++) {
        if (base + i < NBIN) g_rowptr[base + i] = run;
        run += v[i];
    }
    if (t == 0) g_bsum[blockIdx.x] = sh[SCAN_BLK - 1];
}

__global__ __launch_bounds__(256) void scan3() {
    int i = blockIdx.x * 256 + threadIdx.x;
    if (i < NBIN) {
        const int nb = i / SCAN_CHUNK;
        int pre = 0;
        for (int b = 0; b < nb; b++) pre += g_bsum[b];
        int v = g_rowptr[i] + pre;
        g_rowptr[i] = v;
        g_cur[i] = v;
    }
    if (i == 0) g_rowptr[NBIN] = NET;
}

__global__ __launch_bounds__(256) void scatter(const int* __restrict__ erows,
                                               const int* __restrict__ ecols,
                                               const float* __restrict__ evals) {
    int e = blockIdx.x * 256 + threadIdx.x;
    if (e >= NET) return;
    int hop = e / NE;
    int pos = atomicAdd(&g_cur[hop * NN + erows[e]], 1);
    g_edge[pos] = make_int2(ecols[e], __float_as_int(evals[e]));
}

// ---------------------------------------------------------------------------
// GEMM1 (tensor): g_h[n, hop*128+j] = fp16(x @ W[hop] + b[hop])
// Single-pass pure-fp16 mma. CTA 128x128, BK=32, 8 warps (4m x 2n).
// ---------------------------------------------------------------------------
__global__ __launch_bounds__(256) void gemm1_mma(const float* __restrict__ x,
                                                 const float* __restrict__ bias) {
    const int hop = blockIdx.x;
    const int m0  = blockIdx.y * 128;

    __shared__ __half As[128 * SA];
    __shared__ __half Bs[128 * SA];

    const int t    = threadIdx.x;
    const int wid  = t >> 5, lane = t & 31;
    const int wm   = wid >> 1, wn = wid & 1;
    const int g    = lane >> 2, t4 = lane & 3;

    const int lr = t >> 2;          // 0..63
    const int lk = (t & 3) * 8;     // 0,8,16,24

    const __half* wt = g_wt + (size_t)hop * NHID * NF;

    float acc[2][8][4];
#pragma unroll
    for (int i = 0; i < 2; i++)
#pragma unroll
        for (int j = 0; j < 8; j++)
#pragma unroll
            for (int q = 0; q < 4; q++) acc[i][j][q] = 0.f;

    const float4 zf = make_float4(0.f, 0.f, 0.f, 0.f);
    float4 fx0a, fx0b, fx1a, fx1b;
    uint4 pb0, pb1;

    const int r0 = m0 + lr, r1 = m0 + lr + 64;
    {   // prefetch k0 = 0
        fx0a = (r0 < NN) ? *(const float4*)(x + (size_t)r0 * NF + lk)     : zf;
        fx0b = (r0 < NN) ? *(const float4*)(x + (size_t)r0 * NF + lk + 4) : zf;
        fx1a = (r1 < NN) ? *(const float4*)(x + (size_t)r1 * NF + lk)     : zf;
        fx1b = (r1 < NN) ? *(const float4*)(x + (size_t)r1 * NF + lk + 4) : zf;
        pb0  = *(const uint4*)(wt + (size_t)lr * NF + lk);
        pb1  = *(const uint4*)(wt + (size_t)(lr + 64) * NF + lk);
    }

    for (int k0 = 0; k0 < NF; k0 += 32) {
        __syncthreads();
        *(uint4*)&As[lr * SA + lk]        = cvt8(fx0a, fx0b);
        *(uint4*)&As[(lr + 64) * SA + lk] = cvt8(fx1a, fx1b);
        *(uint4*)&Bs[lr * SA + lk]        = pb0;
        *(uint4*)&Bs[(lr + 64) * SA + lk] = pb1;
        __syncthreads();

        const int kn = k0 + 32;
        if (kn < NF) {   // prefetch next K-block
            fx0a = (r0 < NN) ? *(const float4*)(x + (size_t)r0 * NF + kn + lk)     : zf;
            fx0b = (r0 < NN) ? *(const float4*)(x + (size_t)r0 * NF + kn + lk + 4) : zf;
            fx1a = (r1 < NN) ? *(const float4*)(x + (size_t)r1 * NF + kn + lk)     : zf;
            fx1b = (r1 < NN) ? *(const float4*)(x + (size_t)r1 * NF + kn + lk + 4) : zf;
            pb0  = *(const uint4*)(wt + (size_t)lr * NF + kn + lk);
            pb1  = *(const uint4*)(wt + (size_t)(lr + 64) * NF + kn + lk);
        }

#pragma unroll
        for (int ks = 0; ks < 2; ks++) {
            const int kb = ks * 16 + 2 * t4;
            uint32_t a[2][4];
#pragma unroll
            for (int mf = 0; mf < 2; mf++) {
                const int rb = (wm * 32 + mf * 16 + g) * SA + kb;
                a[mf][0] = lds32(&As[rb]);
                a[mf][1] = lds32(&As[rb + 8 * SA]);
                a[mf][2] = lds32(&As[rb + 8]);
                a[mf][3] = lds32(&As[rb + 8 * SA + 8]);
            }
#pragma unroll
            for (int nf = 0; nf < 8; nf++) {
                const int nb = (wn * 64 + nf * 8 + g) * SA + kb;
                uint32_t bb[2];
                bb[0] = lds32(&Bs[nb]); bb[1] = lds32(&Bs[nb + 8]);
#pragma unroll
                for (int mf = 0; mf < 2; mf++)
                    mma16816(acc[mf][nf], a[mf], bb);
            }
        }
    }

    const int colbase = wn * 64 + 2 * t4;
#pragma unroll
    for (int mf = 0; mf < 2; mf++) {
        const int row = m0 + wm * 32 + mf * 16 + g;
#pragma unroll
        for (int nf = 0; nf < 8; nf++) {
            const int col = colbase + nf * 8;
            const float2 bv = *(const float2*)(bias + hop * NHID + col);
            if (row < NN) {
                *(__half2*)(g_h + (size_t)row * NC + hop * NHID + col) =
                    __floats2half2_rn(acc[mf][nf][0] + bv.x, acc[mf][nf][1] + bv.y);
            }
            if (row + 8 < NN) {
                *(__half2*)(g_h + (size_t)(row + 8) * NC + hop * NHID + col) =
                    __floats2half2_rn(acc[mf][nf][2] + bv.x, acc[mf][nf][3] + bv.y);
            }
        }
    }
}

// ---------------------------------------------------------------------------
// CSR SpMM, all hops in one launch. One warp per row, fp32 register
// accumulation, single fp16 write. Lane owns 4 features (8B gather/edge).
// Inner loop identical to the proven R12 version (4-wide unroll, 32 regs).
// ---------------------------------------------------------------------------
__global__ __launch_bounds__(256) void spmm_csr() {
    const int row  = (blockIdx.x * 256 + threadIdx.x) >> 5;
    const int lane = threadIdx.x & 31;
    if (row >= NN) return;
    const int hop = blockIdx.y;

    const int bin = hop * NN + row;
    const int s = g_rowptr[bin];
    const int e = g_rowptr[bin + 1];

    const __half* hb = g_h + hop * NHID + lane * 4;
    float4 acc = make_float4(0.f, 0.f, 0.f, 0.f);

    for (int p = s; p < e; p += 32) {
        const int n = min(32, e - p);
        int2 ed = (lane < n) ? g_edge[p + lane] : make_int2(0, 0);
        const int   c = ed.x;
        const float v = __int_as_float(ed.y);
        int j = 0;
        for (; j + 4 <= n; j += 4) {
            int   c0 = __shfl_sync(0xffffffffu, c, j);
            int   c1 = __shfl_sync(0xffffffffu, c, j + 1);
            int   c2 = __shfl_sync(0xffffffffu, c, j + 2);
            int   c3 = __shfl_sync(0xffffffffu, c, j + 3);
            float v0 = __shfl_sync(0xffffffffu, v, j);
            float v1 = __shfl_sync(0xffffffffu, v, j + 1);
            float v2 = __shfl_sync(0xffffffffu, v, j + 2);
            float v3 = __shfl_sync(0xffffffffu, v, j + 3);
            uint2 u0 = *(const uint2*)(hb + (size_t)c0 * NC);
            uint2 u1 = *(const uint2*)(hb + (size_t)c1 * NC);
            uint2 u2 = *(const uint2*)(hb + (size_t)c2 * NC);
            uint2 u3 = *(const uint2*)(hb + (size_t)c3 * NC);
            float2 a0 = __half22float2(*(__half2*)&u0.x);
            float2 b0 = __half22float2(*(__half2*)&u0.y);
            float2 a1 = __half22float2(*(__half2*)&u1.x);
            float2 b1 = __half22float2(*(__half2*)&u1.y);
            float2 a2 = __half22float2(*(__half2*)&u2.x);
            float2 b2 = __half22float2(*(__half2*)&u2.y);
            float2 a3 = __half22float2(*(__half2*)&u3.x);
            float2 b3 = __half22float2(*(__half2*)&u3.y);
            acc.x = fmaf(v0, a0.x, acc.x); acc.y = fmaf(v0, a0.y, acc.y);
            acc.z = fmaf(v0, b0.x, acc.z); acc.w = fmaf(v0, b0.y, acc.w);
            acc.x = fmaf(v1, a1.x, acc.x); acc.y = fmaf(v1, a1.y, acc.y);
            acc.z = fmaf(v1, b1.x, acc.z); acc.w = fmaf(v1, b1.y, acc.w);
            acc.x = fmaf(v2, a2.x, acc.x); acc.y = fmaf(v2, a2.y, acc.y);
            acc.z = fmaf(v2, b2.x, acc.z); acc.w = fmaf(v2, b2.y, acc.w);
            acc.x = fmaf(v3, a3.x, acc.x); acc.y = fmaf(v3, a3.y, acc.y);
            acc.z = fmaf(v3, b3.x, acc.z); acc.w = fmaf(v3, b3.y, acc.w);
        }
        for (; j < n; j++) {
            int   cj = __shfl_sync(0xffffffffu, c, j);
            float vj = __shfl_sync(0xffffffffu, v, j);
            uint2 u = *(const uint2*)(hb + (size_t)cj * NC);
            float2 a = __half22float2(*(__half2*)&u.x);
            float2 b = __half22float2(*(__half2*)&u.y);
            acc.x = fmaf(vj, a.x, acc.x); acc.y = fmaf(vj, a.y, acc.y);
            acc.z = fmaf(vj, b.x, acc.z); acc.w = fmaf(vj, b.y, acc.w);
        }
    }

    union { uint2 u; __half2 s[2]; } O;
    O.s[0] = __floats2half2_rn(acc.x, acc.y);
    O.s[1] = __floats2half2_rn(acc.z, acc.w);
    *(uint2*)(g_agg + (size_t)row * NC + hop * NHID + lane * 4) = O.u;
}

// ---------------------------------------------------------------------------
// GEMM2 (tensor): y = elu(agg) @ W_out + b_out. agg is fp16; elu applied
// in the A stage (f32 math, fp16 out). CTA 128x64, BK=32, 8 warps (4m x 2n).
// ---------------------------------------------------------------------------
__global__ __launch_bounds__(256) void gemm2_mma(const float* __restrict__ bout,
                                                 float* __restrict__ y) {
    const int m0 = blockIdx.x * 128;

    __shared__ __half As[128 * SA];
    __shared__ __half Bs[64 * SA];

    const int t   = threadIdx.x;
    const int wid = t >> 5, lane = t & 31;
    const int wm  = wid >> 1, wn = wid & 1;
    const int g   = lane >> 2, t4 = lane & 3;

    const int ar = t >> 1;          // A row 0..127
    const int ac = (t & 1) * 16;    // A col block (16 fp16)
    const int br = t >> 2;          // B row (n) 0..63
    const int bk = (t & 3) * 8;     // B col block (8 fp16)

    const int arow = m0 + ar;
    const bool aok = arow < NN;

    float acc[2][4][4];
#pragma unroll
    for (int i = 0; i < 2; i++)
#pragma unroll
        for (int j = 0; j < 4; j++)
#pragma unroll
            for (int q = 0; q < 4; q++) acc[i][j][q] = 0.f;

    const uint4 z4 = make_uint4(0, 0, 0, 0);
    uint4 pa0, pa1, pb;

    {
        const __half* ap = g_agg + (size_t)arow * NC + ac;
        pa0 = aok ? *(const uint4*)(ap)     : z4;
        pa1 = aok ? *(const uint4*)(ap + 8) : z4;
        pb  = *(const uint4*)(g_wot + (size_t)br * NC + bk);
    }

    for (int k0 = 0; k0 < NC; k0 += 32) {
        __syncthreads();
        *(uint4*)&As[ar * SA + ac]     = elu8_h(pa0);
        *(uint4*)&As[ar * SA + ac + 8] = elu8_h(pa1);
        *(uint4*)&Bs[br * SA + bk]     = pb;
        __syncthreads();

        const int kn = k0 + 32;
        if (kn < NC) {
            const __half* ap = g_agg + (size_t)arow * NC + kn + ac;
            pa0 = aok ? *(const uint4*)(ap)     : z4;
            pa1 = aok ? *(const uint4*)(ap + 8) : z4;
            pb  = *(const uint4*)(g_wot + (size_t)br * NC + kn + bk);
        }

#pragma unroll
        for (int ks = 0; ks < 2; ks++) {
            const int kb = ks * 16 + 2 * t4;
            uint32_t a[2][4];
#pragma unroll
            for (int mf = 0; mf < 2; mf++) {
                const int rb = (wm * 32 + mf * 16 + g) * SA + kb;
                a[mf][0] = lds32(&As[rb]);
                a[mf][1] = lds32(&As[rb + 8 * SA]);
                a[mf][2] = lds32(&As[rb + 8]);
                a[mf][3] = lds32(&As[rb + 8 * SA + 8]);
            }
#pragma unroll
            for (int nf = 0; nf < 4; nf++) {
                const int nb = (wn * 32 + nf * 8 + g) * SA + kb;
                uint32_t bb[2];
                bb[0] = lds32(&Bs[nb]); bb[1] = lds32(&Bs[nb + 8]);
#pragma unroll
                for (int mf = 0; mf < 2; mf++)
                    mma16816(acc[mf][nf], a[mf], bb);
            }
        }
    }

    const int colbase = wn * 32 + 2 * t4;
#pragma unroll
    for (int mf = 0; mf < 2; mf++) {
        const int row = m0 + wm * 32 + mf * 16 + g;
#pragma unroll
        for (int nf = 0; nf < 4; nf++) {
            const int col = colbase + nf * 8;
            const float2 bv = *(const float2*)(bout + col);
            if (row < NN) {
                float2 o;
                o.x = acc[mf][nf][0] + bv.x;
                o.y = acc[mf][nf][1] + bv.y;
                *(float2*)(y + (size_t)row * NO + col) = o;
            }
            if (row + 8 < NN) {
                float2 o;
                o.x = acc[mf][nf][2] + bv.x;
                o.y = acc[mf][nf][3] + bv.y;
                *(float2*)(y + (size_t)(row + 8) * NO + col) = o;
            }
        }
    }
}

// ---------------------------------------------------------------------------
// Launch. Inputs: x, W, b, W_out, b_out, edge_rows, edge_cols, edge_vals.
// ---------------------------------------------------------------------------
extern "C" void kernel_launch(void* const* d_in, const int* in_sizes, int n_in,
                              void* d_out, int out_size) {
    (void)in_sizes; (void)n_in; (void)out_size;
    const float* x     = (const float*)d_in[0];
    const float* W     = (const float*)d_in[1];
    const float* b     = (const float*)d_in[2];
    const float* Wout  = (const float*)d_in[3];
    const float* bout  = (const float*)d_in[4];
    const int*   erows = (const int*)d_in[5];
    const int*   ecols = (const int*)d_in[6];
    const float* evals = (const float*)d_in[7];
    float* y = (float*)d_out;

    // prep (zero counters + weight fp16 transposes) and CSR build
    prep<<<(NBIN + 255) / 256, 256>>>(W, Wout);
    hist<<<NET / 256, 256>>>(erows);
    scan1<<<SCAN_NB, SCAN_BLK>>>();
    scan3<<<(NBIN + 255) / 256, 256>>>();
    scatter<<<NET / 256, 256>>>(erows, ecols, evals);

    // per-hop linear on tensor cores (single-pass fp16), fp16 h output
    gemm1_mma<<<dim3(KHOP, (NN + 127) / 128), 256>>>(x, b);

    // CSR SpMM, all hops in one launch (h + agg both L2-resident, fp16)
    spmm_csr<<<dim3((NN * 32 + 255) / 256, KHOP), 256>>>();

    // elu + output projection on tensor cores (fp16 agg in)
    gemm2_mma<<<(NN + 127) / 128, 256>>>(bout, y);
}

// round 17
// speedup vs baseline: 1.1338x; 1.0381x over previous
#include <cuda_runtime.h>
#include <cuda_fp16.h>
#include <math.h>
#include <stdint.h>

#define NN   50000
#define NF   256
#define NHID 128
#define KHOP 4
#define NC   512      // KHOP * NHID
#define NE   800000
#define NO   64
#define SA   40       // smem row stride in fp16 elems (80B, conflict-free frags)

#define NBIN (KHOP * NN)        // 200000 row bins across all hops
#define NET  (KHOP * NE)        // 3200000 edges total
#define SCAN_BLK   256
#define SCAN_PER   16
#define SCAN_CHUNK (SCAN_BLK * SCAN_PER)   // 4096
#define SCAN_NB    49                       // ceil(NBIN / SCAN_CHUNK)

// ---------------------------------------------------------------------------
// Scratch (__device__ globals per harness allocation rules)
// ---------------------------------------------------------------------------
__device__ __half g_h[(size_t)NN * NC];    // post-linear features, fp16 (51.2MB)
__device__ __half g_agg[(size_t)NN * NC];  // SpMM output, fp16 (51.2MB)
__device__ __half g_wt[KHOP * NHID * NF];  // W transposed [hop][n][k], fp16
__device__ __half g_wot[NO * NC];          // W_out transposed [n][k], fp16
// CSR build (recomputed every call; deterministic work)
__device__ int  g_cnt[NBIN];
__device__ int  g_rowptr[NBIN + 1];
__device__ int  g_cur[NBIN];
__device__ int  g_bsum[SCAN_NB];
__device__ int2 g_edge[NET];               // interleaved (col, val-bits)

// ---------------------------------------------------------------------------
// mma.sync m16n8k16 fp16 -> f32, helpers
// ---------------------------------------------------------------------------
__device__ __forceinline__ void mma16816(float* d, const uint32_t* a, const uint32_t* b) {
    asm volatile(
        "mma.sync.aligned.m16n8k16.row.col.f32.f16.f16.f32 "
        "{%0,%1,%2,%3}, {%4,%5,%6,%7}, {%8,%9}, {%0,%1,%2,%3};\n"
        : "+f"(d[0]), "+f"(d[1]), "+f"(d[2]), "+f"(d[3])
        : "r"(a[0]), "r"(a[1]), "r"(a[2]), "r"(a[3]), "r"(b[0]), "r"(b[1]));
}

__device__ __forceinline__ uint32_t lds32(const __half* p) {
    return *reinterpret_cast<const uint32_t*>(p);
}

// convert 8 floats (2x float4) to 8 packed fp16
__device__ __forceinline__ uint4 cvt8(float4 a, float4 b) {
    union { uint4 u; __half2 s[4]; } U;
    U.s[0] = __floats2half2_rn(a.x, a.y);
    U.s[1] = __floats2half2_rn(a.z, a.w);
    U.s[2] = __floats2half2_rn(b.x, b.y);
    U.s[3] = __floats2half2_rn(b.z, b.w);
    return U.u;
}

__device__ __forceinline__ float elu1(float v) {
    return v > 0.f ? v : (__expf(v) - 1.f);
}

// elu over 8 packed halves (fp16 in, fp16 out; math in f32)
__device__ __forceinline__ uint4 elu8_h(uint4 in) {
    union { uint4 u; __half2 s[4]; } I, O;
    I.u = in;
#pragma unroll
    for (int q = 0; q < 4; q++) {
        float2 f = __half22float2(I.s[q]);
        O.s[q] = __floats2half2_rn(elu1(f.x), elu1(f.y));
    }
    return O.u;
}

// ---------------------------------------------------------------------------
// prep_zero: zero CSR counters (side chain).
// prep_w: weight fp16 transposes (main chain, feeds gemm1/gemm2).
// ---------------------------------------------------------------------------
__global__ __launch_bounds__(256) void prep_zero() {
    const int idx = blockIdx.x * 256 + threadIdx.x;
    if (idx < NBIN) g_cnt[idx] = 0;
}

__global__ __launch_bounds__(256) void prep_w(const float* __restrict__ W,
                                              const float* __restrict__ Wout) {
    const int idx = blockIdx.x * 256 + threadIdx.x;
    if (idx < KHOP * NF * NHID) {
        int hop = idx / (NF * NHID);
        int rem = idx - hop * (NF * NHID);
        int k = rem / NHID;
        int n = rem - k * NHID;
        g_wt[(size_t)hop * NHID * NF + (size_t)n * NF + k] = __float2half_rn(W[idx]);
    }
    if (idx < NC * NO) {
        int k = idx / NO;
        int n = idx - k * NO;
        g_wot[(size_t)n * NC + k] = __float2half_rn(Wout[idx]);
    }
}

// ---------------------------------------------------------------------------
// CSR build: histogram -> two-level scan -> scatter (global across hops).
// ---------------------------------------------------------------------------
__global__ __launch_bounds__(256) void hist(const int* __restrict__ erows) {
    int e = blockIdx.x * 256 + threadIdx.x;
    if (e >= NET) return;
    int hop = e / NE;
    atomicAdd(&g_cnt[hop * NN + erows[e]], 1);
}

__global__ __launch_bounds__(SCAN_BLK) void scan1() {
    __shared__ int sh[SCAN_BLK];
    const int t = threadIdx.x;
    const int base = blockIdx.x * SCAN_CHUNK + t * SCAN_PER;
    int v[SCAN_PER];
    int tot = 0;
#pragma unroll
    for (int i = 0; i < SCAN_PER; i++) {
        v[i] = (base + i < NBIN) ? g_cnt[base + i] : 0;
        tot += v[i];
    }
    sh[t] = tot;
    __syncthreads();
    for (int off = 1; off < SCAN_BLK; off <<= 1) {
        int x = (t >= off) ? sh[t - off] : 0;
        __syncthreads();
        sh[t] += x;
        __syncthreads();
    }
    int run = sh[t] - tot;
#pragma unroll
    for (int i = 0; i < SCAN_PER; i++) {
        if (base + i < NBIN) g_rowptr[base + i] = run;
        run += v[i];
    }
    if (t == 0) g_bsum[blockIdx.x] = sh[SCAN_BLK - 1];
}

__global__ __launch_bounds__(256) void scan3() {
    int i = blockIdx.x * 256 + threadIdx.x;
    if (i < NBIN) {
        const int nb = i / SCAN_CHUNK;
        int pre = 0;
        for (int b = 0; b < nb; b++) pre += g_bsum[b];
        int v = g_rowptr[i] + pre;
        g_rowptr[i] = v;
        g_cur[i] = v;
    }
    if (i == 0) g_rowptr[NBIN] = NET;
}

__global__ __launch_bounds__(256) void scatter(const int* __restrict__ erows,
                                               const int* __restrict__ ecols,
                                               const float* __restrict__ evals) {
    int e = blockIdx.x * 256 + threadIdx.x;
    if (e >= NET) return;
    int hop = e / NE;
    int pos = atomicAdd(&g_cur[hop * NN + erows[e]], 1);
    g_edge[pos] = make_int2(ecols[e], __float_as_int(evals[e]));
}

// ---------------------------------------------------------------------------
// GEMM1 (tensor): g_h[n, hop*128+j] = fp16(x @ W[hop] + b[hop])
// Single-pass pure-fp16 mma. CTA 128x128, BK=32, 8 warps (4m x 2n).
// ---------------------------------------------------------------------------
__global__ __launch_bounds__(256) void gemm1_mma(const float* __restrict__ x,
                                                 const float* __restrict__ bias) {
    const int hop = blockIdx.x;
    const int m0  = blockIdx.y * 128;

    __shared__ __half As[128 * SA];
    __shared__ __half Bs[128 * SA];

    const int t    = threadIdx.x;
    const int wid  = t >> 5, lane = t & 31;
    const int wm   = wid >> 1, wn = wid & 1;
    const int g    = lane >> 2, t4 = lane & 3;

    const int lr = t >> 2;          // 0..63
    const int lk = (t & 3) * 8;     // 0,8,16,24

    const __half* wt = g_wt + (size_t)hop * NHID * NF;

    float acc[2][8][4];
#pragma unroll
    for (int i = 0; i < 2; i++)
#pragma unroll
        for (int j = 0; j < 8; j++)
#pragma unroll
            for (int q = 0; q < 4; q++) acc[i][j][q] = 0.f;

    const float4 zf = make_float4(0.f, 0.f, 0.f, 0.f);
    float4 fx0a, fx0b, fx1a, fx1b;
    uint4 pb0, pb1;

    const int r0 = m0 + lr, r1 = m0 + lr + 64;
    {   // prefetch k0 = 0
        fx0a = (r0 < NN) ? *(const float4*)(x + (size_t)r0 * NF + lk)     : zf;
        fx0b = (r0 < NN) ? *(const float4*)(x + (size_t)r0 * NF + lk + 4) : zf;
        fx1a = (r1 < NN) ? *(const float4*)(x + (size_t)r1 * NF + lk)     : zf;
        fx1b = (r1 < NN) ? *(const float4*)(x + (size_t)r1 * NF + lk + 4) : zf;
        pb0  = *(const uint4*)(wt + (size_t)lr * NF + lk);
        pb1  = *(const uint4*)(wt + (size_t)(lr + 64) * NF + lk);
    }

    for (int k0 = 0; k0 < NF; k0 += 32) {
        __syncthreads();
        *(uint4*)&As[lr * SA + lk]        = cvt8(fx0a, fx0b);
        *(uint4*)&As[(lr + 64) * SA + lk] = cvt8(fx1a, fx1b);
        *(uint4*)&Bs[lr * SA + lk]        = pb0;
        *(uint4*)&Bs[(lr + 64) * SA + lk] = pb1;
        __syncthreads();

        const int kn = k0 + 32;
        if (kn < NF) {   // prefetch next K-block
            fx0a = (r0 < NN) ? *(const float4*)(x + (size_t)r0 * NF + kn + lk)     : zf;
            fx0b = (r0 < NN) ? *(const float4*)(x + (size_t)r0 * NF + kn + lk + 4) : zf;
            fx1a = (r1 < NN) ? *(const float4*)(x + (size_t)r1 * NF + kn + lk)     : zf;
            fx1b = (r1 < NN) ? *(const float4*)(x + (size_t)r1 * NF + kn + lk + 4) : zf;
            pb0  = *(const uint4*)(wt + (size_t)lr * NF + kn + lk);
            pb1  = *(const uint4*)(wt + (size_t)(lr + 64) * NF + kn + lk);
        }

#pragma unroll
        for (int ks = 0; ks < 2; ks++) {
            const int kb = ks * 16 + 2 * t4;
            uint32_t a[2][4];
#pragma unroll
            for (int mf = 0; mf < 2; mf++) {
                const int rb = (wm * 32 + mf * 16 + g) * SA + kb;
                a[mf][0] = lds32(&As[rb]);
                a[mf][1] = lds32(&As[rb + 8 * SA]);
                a[mf][2] = lds32(&As[rb + 8]);
                a[mf][3] = lds32(&As[rb + 8 * SA + 8]);
            }
#pragma unroll
            for (int nf = 0; nf < 8; nf++) {
                const int nb = (wn * 64 + nf * 8 + g) * SA + kb;
                uint32_t bb[2];
                bb[0] = lds32(&Bs[nb]); bb[1] = lds32(&Bs[nb + 8]);
#pragma unroll
                for (int mf = 0; mf < 2; mf++)
                    mma16816(acc[mf][nf], a[mf], bb);
            }
        }
    }

    const int colbase = wn * 64 + 2 * t4;
#pragma unroll
    for (int mf = 0; mf < 2; mf++) {
        const int row = m0 + wm * 32 + mf * 16 + g;
#pragma unroll
        for (int nf = 0; nf < 8; nf++) {
            const int col = colbase + nf * 8;
            const float2 bv = *(const float2*)(bias + hop * NHID + col);
            if (row < NN) {
                *(__half2*)(g_h + (size_t)row * NC + hop * NHID + col) =
                    __floats2half2_rn(acc[mf][nf][0] + bv.x, acc[mf][nf][1] + bv.y);
            }
            if (row + 8 < NN) {
                *(__half2*)(g_h + (size_t)(row + 8) * NC + hop * NHID + col) =
                    __floats2half2_rn(acc[mf][nf][2] + bv.x, acc[mf][nf][3] + bv.y);
            }
        }
    }
}

// ---------------------------------------------------------------------------
// CSR SpMM, all hops in one launch. One warp per row, fp32 register
// accumulation, single fp16 write. Lane owns 4 features (8B gather/edge).
// Proven 4-wide unroll (32 regs).
// ---------------------------------------------------------------------------
__global__ __launch_bounds__(256) void spmm_csr() {
    const int row  = (blockIdx.x * 256 + threadIdx.x) >> 5;
    const int lane = threadIdx.x & 31;
    if (row >= NN) return;
    const int hop = blockIdx.y;

    const int bin = hop * NN + row;
    const int s = g_rowptr[bin];
    const int e = g_rowptr[bin + 1];

    const __half* hb = g_h + hop * NHID + lane * 4;
    float4 acc = make_float4(0.f, 0.f, 0.f, 0.f);

    for (int p = s; p < e; p += 32) {
        const int n = min(32, e - p);
        int2 ed = (lane < n) ? g_edge[p + lane] : make_int2(0, 0);
        const int   c = ed.x;
        const float v = __int_as_float(ed.y);
        int j = 0;
        for (; j + 4 <= n; j += 4) {
            int   c0 = __shfl_sync(0xffffffffu, c, j);
            int   c1 = __shfl_sync(0xffffffffu, c, j + 1);
            int   c2 = __shfl_sync(0xffffffffu, c, j + 2);
            int   c3 = __shfl_sync(0xffffffffu, c, j + 3);
            float v0 = __shfl_sync(0xffffffffu, v, j);
            float v1 = __shfl_sync(0xffffffffu, v, j + 1);
            float v2 = __shfl_sync(0xffffffffu, v, j + 2);
            float v3 = __shfl_sync(0xffffffffu, v, j + 3);
            uint2 u0 = *(const uint2*)(hb + (size_t)c0 * NC);
            uint2 u1 = *(const uint2*)(hb + (size_t)c1 * NC);
            uint2 u2 = *(const uint2*)(hb + (size_t)c2 * NC);
            uint2 u3 = *(const uint2*)(hb + (size_t)c3 * NC);
            float2 a0 = __half22float2(*(__half2*)&u0.x);
            float2 b0 = __half22float2(*(__half2*)&u0.y);
            float2 a1 = __half22float2(*(__half2*)&u1.x);
            float2 b1 = __half22float2(*(__half2*)&u1.y);
            float2 a2 = __half22float2(*(__half2*)&u2.x);
            float2 b2 = __half22float2(*(__half2*)&u2.y);
            float2 a3 = __half22float2(*(__half2*)&u3.x);
            float2 b3 = __half22float2(*(__half2*)&u3.y);
            acc.x = fmaf(v0, a0.x, acc.x); acc.y = fmaf(v0, a0.y, acc.y);
            acc.z = fmaf(v0, b0.x, acc.z); acc.w = fmaf(v0, b0.y, acc.w);
            acc.x = fmaf(v1, a1.x, acc.x); acc.y = fmaf(v1, a1.y, acc.y);
            acc.z = fmaf(v1, b1.x, acc.z); acc.w = fmaf(v1, b1.y, acc.w);
            acc.x = fmaf(v2, a2.x, acc.x); acc.y = fmaf(v2, a2.y, acc.y);
            acc.z = fmaf(v2, b2.x, acc.z); acc.w = fmaf(v2, b2.y, acc.w);
            acc.x = fmaf(v3, a3.x, acc.x); acc.y = fmaf(v3, a3.y, acc.y);
            acc.z = fmaf(v3, b3.x, acc.z); acc.w = fmaf(v3, b3.y, acc.w);
        }
        for (; j < n; j++) {
            int   cj = __shfl_sync(0xffffffffu, c, j);
            float vj = __shfl_sync(0xffffffffu, v, j);
            uint2 u = *(const uint2*)(hb + (size_t)cj * NC);
            float2 a = __half22float2(*(__half2*)&u.x);
            float2 b = __half22float2(*(__half2*)&u.y);
            acc.x = fmaf(vj, a.x, acc.x); acc.y = fmaf(vj, a.y, acc.y);
            acc.z = fmaf(vj, b.x, acc.z); acc.w = fmaf(vj, b.y, acc.w);
        }
    }

    union { uint2 u; __half2 s[2]; } O;
    O.s[0] = __floats2half2_rn(acc.x, acc.y);
    O.s[1] = __floats2half2_rn(acc.z, acc.w);
    *(uint2*)(g_agg + (size_t)row * NC + hop * NHID + lane * 4) = O.u;
}

// ---------------------------------------------------------------------------
// GEMM2 (tensor): y = elu(agg) @ W_out + b_out. agg is fp16; elu applied
// in the A stage (f32 math, fp16 out). CTA 128x64, BK=32, 8 warps (4m x 2n).
// ---------------------------------------------------------------------------
__global__ __launch_bounds__(256) void gemm2_mma(const float* __restrict__ bout,
                                                 float* __restrict__ y) {
    const int m0 = blockIdx.x * 128;

    __shared__ __half As[128 * SA];
    __shared__ __half Bs[64 * SA];

    const int t   = threadIdx.x;
    const int wid = t >> 5, lane = t & 31;
    const int wm  = wid >> 1, wn = wid & 1;
    const int g   = lane >> 2, t4 = lane & 3;

    const int ar = t >> 1;          // A row 0..127
    const int ac = (t & 1) * 16;    // A col block (16 fp16)
    const int br = t >> 2;          // B row (n) 0..63
    const int bk = (t & 3) * 8;     // B col block (8 fp16)

    const int arow = m0 + ar;
    const bool aok = arow < NN;

    float acc[2][4][4];
#pragma unroll
    for (int i = 0; i < 2; i++)
#pragma unroll
        for (int j = 0; j < 4; j++)
#pragma unroll
            for (int q = 0; q < 4; q++) acc[i][j][q] = 0.f;

    const uint4 z4 = make_uint4(0, 0, 0, 0);
    uint4 pa0, pa1, pb;

    {
        const __half* ap = g_agg + (size_t)arow * NC + ac;
        pa0 = aok ? *(const uint4*)(ap)     : z4;
        pa1 = aok ? *(const uint4*)(ap + 8) : z4;
        pb  = *(const uint4*)(g_wot + (size_t)br * NC + bk);
    }

    for (int k0 = 0; k0 < NC; k0 += 32) {
        __syncthreads();
        *(uint4*)&As[ar * SA + ac]     = elu8_h(pa0);
        *(uint4*)&As[ar * SA + ac + 8] = elu8_h(pa1);
        *(uint4*)&Bs[br * SA + bk]     = pb;
        __syncthreads();

        const int kn = k0 + 32;
        if (kn < NC) {
            const __half* ap = g_agg + (size_t)arow * NC + kn + ac;
            pa0 = aok ? *(const uint4*)(ap)     : z4;
            pa1 = aok ? *(const uint4*)(ap + 8) : z4;
            pb  = *(const uint4*)(g_wot + (size_t)br * NC + kn + bk);
        }

#pragma unroll
        for (int ks = 0; ks < 2; ks++) {
            const int kb = ks * 16 + 2 * t4;
            uint32_t a[2][4];
#pragma unroll
            for (int mf = 0; mf < 2; mf++) {
                const int rb = (wm * 32 + mf * 16 + g) * SA + kb;
                a[mf][0] = lds32(&As[rb]);
                a[mf][1] = lds32(&As[rb + 8 * SA]);
                a[mf][2] = lds32(&As[rb + 8]);
                a[mf][3] = lds32(&As[rb + 8 * SA + 8]);
            }
#pragma unroll
            for (int nf = 0; nf < 4; nf++) {
                const int nb = (wn * 32 + nf * 8 + g) * SA + kb;
                uint32_t bb[2];
                bb[0] = lds32(&Bs[nb]); bb[1] = lds32(&Bs[nb + 8]);
#pragma unroll
                for (int mf = 0; mf < 2; mf++)
                    mma16816(acc[mf][nf], a[mf], bb);
            }
        }
    }

    const int colbase = wn * 32 + 2 * t4;
#pragma unroll
    for (int mf = 0; mf < 2; mf++) {
        const int row = m0 + wm * 32 + mf * 16 + g;
#pragma unroll
        for (int nf = 0; nf < 4; nf++) {
            const int col = colbase + nf * 8;
            const float2 bv = *(const float2*)(bout + col);
            if (row < NN) {
                float2 o;
                o.x = acc[mf][nf][0] + bv.x;
                o.y = acc[mf][nf][1] + bv.y;
                *(float2*)(y + (size_t)row * NO + col) = o;
            }
            if (row + 8 < NN) {
                float2 o;
                o.x = acc[mf][nf][2] + bv.x;
                o.y = acc[mf][nf][3] + bv.y;
                *(float2*)(y + (size_t)(row + 8) * NO + col) = o;
            }
        }
    }
}

// ---------------------------------------------------------------------------
// Launch. Inputs: x, W, b, W_out, b_out, edge_rows, edge_cols, edge_vals.
// CSR build (edges only) forked onto a second stream, overlapping with
// prep_w + gemm1 (x/W only); joined before spmm which needs both.
// Stream/events created per call (kernel_launch runs only a few times;
// host-side handles, no device allocation, deterministic work).
// ---------------------------------------------------------------------------
extern "C" void kernel_launch(void* const* d_in, const int* in_sizes, int n_in,
                              void* d_out, int out_size) {
    (void)in_sizes; (void)n_in; (void)out_size;
    const float* x     = (const float*)d_in[0];
    const float* W     = (const float*)d_in[1];
    const float* b     = (const float*)d_in[2];
    const float* Wout  = (const float*)d_in[3];
    const float* bout  = (const float*)d_in[4];
    const int*   erows = (const int*)d_in[5];
    const int*   ecols = (const int*)d_in[6];
    const float* evals = (const float*)d_in[7];
    float* y = (float*)d_out;

    cudaStream_t s2;
    cudaStreamCreateWithFlags(&s2, cudaStreamNonBlocking);
    cudaEvent_t evFork, evJoin;
    cudaEventCreateWithFlags(&evFork, cudaEventDisableTiming);
    cudaEventCreateWithFlags(&evJoin, cudaEventDisableTiming);

    // fork: side stream joins the capture
    cudaEventRecord(evFork, 0);
    cudaStreamWaitEvent(s2, evFork, 0);

    // side chain: CSR build (depends only on edge inputs)
    prep_zero<<<(NBIN + 255) / 256, 256, 0, s2>>>();
    hist<<<NET / 256, 256, 0, s2>>>(erows);
    scan1<<<SCAN_NB, SCAN_BLK, 0, s2>>>();
    scan3<<<(NBIN + 255) / 256, 256, 0, s2>>>();
    scatter<<<NET / 256, 256, 0, s2>>>(erows, ecols, evals);
    cudaEventRecord(evJoin, s2);

    // main chain: weight conversion + per-hop linear (depends on x, W, b)
    prep_w<<<(KHOP * NF * NHID + 255) / 256, 256>>>(W, Wout);
    gemm1_mma<<<dim3(KHOP, (NN + 127) / 128), 256>>>(x, b);

    // join: spmm needs CSR (side) + g_h (main)
    cudaStreamWaitEvent(0, evJoin, 0);

    spmm_csr<<<dim3((NN * 32 + 255) / 256, KHOP), 256>>>();
    gemm2_mma<<<(NN + 127) / 128, 256>>>(bout, y);
}